// round 9
// baseline (speedup 1.0000x reference)
#include <cuda_runtime.h>
#include <cuda_bf16.h>
#include <math.h>
#include <stdint.h>

// Problem constants (shape-fixed per reference)
#define NN   50000
#define NE   800000
#define DIM  128
#define NH   8
#define HD   16

// -------- scratch in __device__ globals (no runtime allocation allowed) -----
__device__ float g_Q[NN * DIM];
__device__ float g_K[NN * DIM];
__device__ float g_V[NN * DIM];
__device__ float g_E[(size_t)NE * DIM];   // 409.6 MB
__device__ float g_Z[NN * NH];
// Pre-swizzled bf16 weight images (hi / lo split), 4 matrices (q,k,v,e)
__device__ __nv_bfloat16 g_W1img[4][DIM * DIM];
__device__ __nv_bfloat16 g_W2img[4][DIM * DIM];

// ---------------------------------------------------------------------------
__device__ __forceinline__ uint32_t smem_u32(const void* p) {
    uint32_t a;
    asm("{ .reg .u64 t; cvta.to.shared.u64 t, %1; cvt.u32.u64 %0, t; }"
        : "=r"(a) : "l"(p));
    return a;
}

// Swizzled byte offset inside a [rows x 128] bf16 tile (256B rows).
__device__ __forceinline__ uint32_t soff(int r, int k) {
    uint32_t u = (uint32_t)(k >> 3);
    uint32_t us = (u & 8u) | ((u ^ (uint32_t)(r & 7)) & 7u);
    return (uint32_t)r * 256u + us * 16u + (uint32_t)(k & 7) * 2u;
}

// Non-volatile (schedulable) ldmatrix with memory clobber.
__device__ __forceinline__ void ldsm_x4(uint32_t* r, uint32_t addr) {
    asm("ldmatrix.sync.aligned.m8n8.x4.shared.b16 {%0,%1,%2,%3}, [%4];"
        : "=r"(r[0]), "=r"(r[1]), "=r"(r[2]), "=r"(r[3]) : "r"(addr) : "memory");
}

__device__ __forceinline__ void mma16816(float* d, const uint32_t* a,
                                         uint32_t b0, uint32_t b1) {
    asm("mma.sync.aligned.m16n8k16.row.col.f32.bf16.bf16.f32 "
        "{%0,%1,%2,%3}, {%4,%5,%6,%7}, {%8,%9}, {%0,%1,%2,%3};"
        : "+f"(d[0]), "+f"(d[1]), "+f"(d[2]), "+f"(d[3])
        : "r"(a[0]), "r"(a[1]), "r"(a[2]), "r"(a[3]), "r"(b0), "r"(b1));
}

// ---------------- weight prep: fp32 W[k,n] -> swizzled bf16 hi/lo images -----
__global__ __launch_bounds__(256)
void prep_w_kernel(const float* __restrict__ W0, const float* __restrict__ W1,
                   const float* __restrict__ W2, const float* __restrict__ W3,
                   __nv_bfloat16* __restrict__ img1, __nv_bfloat16* __restrict__ img2) {
    int gi = blockIdx.x * 256 + threadIdx.x;
    if (gi >= 4 * DIM * DIM) return;
    int m = gi >> 14;
    int i = gi & (DIM * DIM - 1);
    const float* W = (m == 0) ? W0 : (m == 1) ? W1 : (m == 2) ? W2 : W3;
    int k = i >> 7;
    int n = i & 127;
    float a = W[i];
    __nv_bfloat16 h = __float2bfloat16(a);
    float lo = a - __bfloat162float(h);
    uint32_t off = soff(n, k);
    *(__nv_bfloat16*)((char*)(img1 + (size_t)m * DIM * DIM) + off) = h;
    *(__nv_bfloat16*)((char*)(img2 + (size_t)m * DIM * DIM) + off) = __float2bfloat16(lo);
}

// ----------- GEMM core: C[M,128] = X[M,128]@W + b, M-tile 64, 256 thr -------
// 8 warps in 2(M)x4(N) grid, 32x32 warp tiles. 2 CTAs/SM (97K smem each).
// smem: bias 1K | A1 16K | A2 16K | W1 32K | W2 32K = 97K
#define SM_BIAS  0
#define SM_A1    1024
#define SM_A2    (1024 + 16384)
#define SM_W1    (1024 + 32768)
#define SM_W2    (1024 + 65536)
#define SM_TOTAL (1024 + 98304)
#define GTHREADS 256

__device__ __forceinline__ void gemm_core(
    const float* __restrict__ X,
    const __nv_bfloat16* __restrict__ W1img,
    const __nv_bfloat16* __restrict__ W2img,
    const float* __restrict__ bias,
    float* __restrict__ C, int M, int nT, int t0, int ts)
{
    extern __shared__ char smem[];
    const uint32_t sb = smem_u32(smem);
    const int tid = threadIdx.x;
    const int wid = tid >> 5;
    const int lid = tid & 31;

    // ---- one-time: weights + bias into smem ----
    {
        const int4* s1 = (const int4*)W1img;
        const int4* s2 = (const int4*)W2img;
        int4* d1 = (int4*)(smem + SM_W1);
        int4* d2 = (int4*)(smem + SM_W2);
        #pragma unroll
        for (int i = tid; i < 2048; i += GTHREADS) {
            d1[i] = s1[i];
            d2[i] = s2[i];
        }
    }
    if (tid < 128) *(float*)(smem + SM_BIAS + tid * 4) = bias[tid];

    // ---- per-thread convert slots (tile-invariant): j = tid + w*256 ----
    uint32_t preoff[8];
    int      xoff[8];
    #pragma unroll
    for (int w = 0; w < 8; w++) {
        int j  = tid + w * GTHREADS;
        int r  = j >> 5;              // 0..63
        int k4 = (j & 31) << 2;
        preoff[w] = soff(r, k4);
        xoff[w]   = r * DIM + k4;
    }

    auto ldg8 = [&](int t, float4* vb) {
        const size_t base = (size_t)t * 64 * DIM;
        const int lim = (M - t * 64) * DIM;
        #pragma unroll
        for (int w = 0; w < 8; w++)
            vb[w] = (xoff[w] < lim) ? *(const float4*)(X + base + xoff[w])
                                    : make_float4(0.f, 0.f, 0.f, 0.f);
    };
    auto cvt8 = [&](const float4* vb) {
        #pragma unroll
        for (int w = 0; w < 8; w++) {
            float4 v = vb[w];
            __nv_bfloat162 hp0 = __floats2bfloat162_rn(v.x, v.y);
            __nv_bfloat162 hp1 = __floats2bfloat162_rn(v.z, v.w);
            __nv_bfloat162 lp0 = __floats2bfloat162_rn(v.x - __bfloat162float(hp0.x),
                                                       v.y - __bfloat162float(hp0.y));
            __nv_bfloat162 lp1 = __floats2bfloat162_rn(v.z - __bfloat162float(hp1.x),
                                                       v.w - __bfloat162float(hp1.y));
            uint2 hq, lq;
            hq.x = *(uint32_t*)&hp0; hq.y = *(uint32_t*)&hp1;
            lq.x = *(uint32_t*)&lp0; lq.y = *(uint32_t*)&lp1;
            *(uint2*)(smem + SM_A1 + preoff[w]) = hq;
            *(uint2*)(smem + SM_A2 + preoff[w]) = lq;
        }
    };

    const int wm = (wid >> 2) * 32;   // 0 or 32
    const int wn = (wid & 3) * 32;    // 0,32,64,96
    const int g  = lid >> 3;
    const int lr = (lid & 7) | ((g & 1) << 3);
    const int kq = (g >> 1) << 3;
    const int cr = lid >> 2;
    const int cc = (lid & 3) * 2;
    const float* sBias = (const float*)(smem + SM_BIAS);

    // prologue
    float4 vb[8];
    if (t0 < nT) ldg8(t0, vb);
    __syncthreads();                  // weights/bias visible
    if (t0 < nT) cvt8(vb);
    __syncthreads();                  // A tile ready

    for (int t = t0; t < nT; t += ts) {
        float acc[2][4][4];
        #pragma unroll
        for (int i = 0; i < 2; i++)
            #pragma unroll
            for (int j = 0; j < 4; j++)
                #pragma unroll
                for (int u = 0; u < 4; u++) acc[i][j][u] = 0.f;

        // ---- MMA: C = A1*W1 + A2*W1 + A1*W2 ----
        #pragma unroll
        for (int ks = 0; ks < 8; ks++) {
            const int k0 = ks * 16 + kq;
            uint32_t a1f[2][4], a2f[2][4], b1f[2][4], b2f[2][4];
            #pragma unroll
            for (int mt = 0; mt < 2; mt++) {
                ldsm_x4(a1f[mt], sb + SM_A1 + soff(wm + mt * 16 + lr, k0));
                ldsm_x4(a2f[mt], sb + SM_A2 + soff(wm + mt * 16 + lr, k0));
            }
            #pragma unroll
            for (int nt2 = 0; nt2 < 2; nt2++) {
                ldsm_x4(b1f[nt2], sb + SM_W1 + soff(wn + nt2 * 16 + lr, k0));
                ldsm_x4(b2f[nt2], sb + SM_W2 + soff(wn + nt2 * 16 + lr, k0));
            }
            #pragma unroll
            for (int mt = 0; mt < 2; mt++) {
                mma16816(acc[mt][0], a1f[mt], b1f[0][0], b1f[0][2]);
                mma16816(acc[mt][1], a1f[mt], b1f[0][1], b1f[0][3]);
                mma16816(acc[mt][2], a1f[mt], b1f[1][0], b1f[1][2]);
                mma16816(acc[mt][3], a1f[mt], b1f[1][1], b1f[1][3]);
            }
            #pragma unroll
            for (int mt = 0; mt < 2; mt++) {
                mma16816(acc[mt][0], a2f[mt], b1f[0][0], b1f[0][2]);
                mma16816(acc[mt][1], a2f[mt], b1f[0][1], b1f[0][3]);
                mma16816(acc[mt][2], a2f[mt], b1f[1][0], b1f[1][2]);
                mma16816(acc[mt][3], a2f[mt], b1f[1][1], b1f[1][3]);
            }
            #pragma unroll
            for (int mt = 0; mt < 2; mt++) {
                mma16816(acc[mt][0], a1f[mt], b2f[0][0], b2f[0][2]);
                mma16816(acc[mt][1], a1f[mt], b2f[0][1], b2f[0][3]);
                mma16816(acc[mt][2], a1f[mt], b2f[1][0], b2f[1][2]);
                mma16816(acc[mt][3], a1f[mt], b2f[1][1], b2f[1][3]);
            }
        }

        // start next tile's LDG (results awaited at cvt after the sync)
        const int tn = t + ts;
        if (tn < nT) ldg8(tn, vb);

        // epilogue
        const int row0 = t * 64;
        #pragma unroll
        for (int mt = 0; mt < 2; mt++) {
            #pragma unroll
            for (int nt = 0; nt < 4; nt++) {
                int col = wn + nt * 8 + cc;
                float b0 = sBias[col], b1 = sBias[col + 1];
                int r1 = row0 + wm + mt * 16 + cr;
                if (r1 < M) {
                    float2 o; o.x = acc[mt][nt][0] + b0; o.y = acc[mt][nt][1] + b1;
                    *(float2*)(C + (size_t)r1 * DIM + col) = o;
                }
                int r2 = r1 + 8;
                if (r2 < M) {
                    float2 o; o.x = acc[mt][nt][2] + b0; o.y = acc[mt][nt][3] + b1;
                    *(float2*)(C + (size_t)r2 * DIM + col) = o;
                }
            }
        }
        __syncthreads();              // all LDSM reads of A done
        if (tn < nT) cvt8(vb);
        __syncthreads();              // A tile (t+1) ready
    }
}

// QKV fused: m = blockIdx.x % 3 selects matrix; tiles grid-strided per m.
__global__ __launch_bounds__(GTHREADS, 2)
void qkv_gemm_kernel(const float* __restrict__ X,
                     const float* __restrict__ bq, const float* __restrict__ bk,
                     const float* __restrict__ bv, int M, int nT) {
    const int m  = blockIdx.x % 3;
    const int t0 = blockIdx.x / 3;
    const int ts = gridDim.x / 3;
    const float* bias = (m == 0) ? bq : (m == 1) ? bk : bv;
    float* C = (m == 0) ? g_Q : (m == 1) ? g_K : g_V;
    gemm_core(X, g_W1img[m], g_W2img[m], bias, C, M, nT, t0, ts);
}

__global__ __launch_bounds__(GTHREADS, 2)
void e_gemm_kernel(const float* __restrict__ EA, const float* __restrict__ be,
                   int M, int nT) {
    gemm_core(EA, g_W1img[3], g_W2img[3], be, g_E, M, nT, blockIdx.x, gridDim.x);
}

// --------------------------- edge scatter kernel ----------------------------
__device__ __forceinline__ void red4(float* p, float a, float b, float c, float d) {
    asm volatile("red.global.add.v4.f32 [%0], {%1, %2, %3, %4};"
                 :: "l"(p), "f"(a), "f"(b), "f"(c), "f"(d) : "memory");
}

__global__ __launch_bounds__(256)
void edge_kernel(const int* __restrict__ ei, const float* __restrict__ E,
                 float* __restrict__ wV, int nE) {
    const int lid   = threadIdx.x & 31;
    const int warp  = (blockIdx.x * blockDim.x + threadIdx.x) >> 5;
    const int nwarp = (gridDim.x * blockDim.x) >> 5;
    const int h  = lid >> 2;
    const int i4 = lid & 3;

    for (int e = warp; e < nE; e += nwarp) {
        int src = __ldg(ei + e);
        int dst = __ldg(ei + nE + e);

        float4 k  = *(const float4*)(g_K + (size_t)src * DIM + 4 * lid);
        float4 q  = *(const float4*)(g_Q + (size_t)dst * DIM + 4 * lid);
        float4 ev = __ldg((const float4*)(E + (size_t)e * DIM + 4 * lid));

        float t = k.x * q.x * ev.x + k.y * q.y * ev.y
                + k.z * q.z * ev.z + k.w * q.w * ev.w;
        t += __shfl_xor_sync(0xFFFFFFFFu, t, 1);
        t += __shfl_xor_sync(0xFFFFFFFFu, t, 2);
        t *= 0.25f;                          // 1/sqrt(16)
        t = fminf(fmaxf(t, -5.f), 5.f);
        float s = __expf(t);

        float4 v = *(const float4*)(g_V + (size_t)src * DIM + 4 * lid);
        red4(wV + (size_t)dst * DIM + 4 * lid, v.x * s, v.y * s, v.z * s, v.w * s);
        if (i4 == 0) atomicAdd(&g_Z[dst * NH + h], s);
    }
}

// ----------------------------- normalize ------------------------------------
__global__ __launch_bounds__(256)
void normalize_kernel(float* __restrict__ out, int n) {
    int i = blockIdx.x * blockDim.x + threadIdx.x;
    if (i >= n) return;
    int node = i >> 7;
    int h    = (i >> 4) & 7;
    float z = g_Z[node * NH + h];
    out[i] = out[i] / (z + 1e-6f);
}

// ----------------------------- launcher -------------------------------------
extern "C" void kernel_launch(void* const* d_in, const int* in_sizes, int n_in,
                              void* d_out, int out_size) {
    const float* x   = (const float*)d_in[0];
    const float* ea  = (const float*)d_in[1];
    const int*   ei  = (const int*)d_in[2];
    const float* Wq  = (const float*)d_in[3];
    const float* bq  = (const float*)d_in[4];
    const float* Wk  = (const float*)d_in[5];
    const float* bk  = (const float*)d_in[6];
    const float* We  = (const float*)d_in[7];
    const float* be  = (const float*)d_in[8];
    const float* Wv  = (const float*)d_in[9];
    const float* bv  = (const float*)d_in[10];
    float* out = (float*)d_out;

    const int nN = in_sizes[0] / DIM;     // 50000
    const int nE = in_sizes[1] / DIM;     // 800000

    float *pE, *pZ;
    cudaGetSymbolAddress((void**)&pE, g_E);
    cudaGetSymbolAddress((void**)&pZ, g_Z);
    {
        __nv_bfloat16 *pW1, *pW2;
        cudaGetSymbolAddress((void**)&pW1, g_W1img);
        cudaGetSymbolAddress((void**)&pW2, g_W2img);
        cudaMemsetAsync(d_out, 0, (size_t)out_size * sizeof(float));
        cudaMemsetAsync(pZ, 0, (size_t)nN * NH * sizeof(float));
        prep_w_kernel<<<(4 * DIM * DIM + 255) / 256, 256>>>(Wq, Wk, Wv, We, pW1, pW2);
    }

    cudaFuncSetAttribute(qkv_gemm_kernel, cudaFuncAttributeMaxDynamicSharedMemorySize, SM_TOTAL);
    cudaFuncSetAttribute(e_gemm_kernel,   cudaFuncAttributeMaxDynamicSharedMemorySize, SM_TOTAL);

    int tN = (nN + 63) / 64;      // 782
    int tE = (nE + 63) / 64;      // 12500
    qkv_gemm_kernel<<<294, GTHREADS, SM_TOTAL>>>(x, bq, bk, bv, nN, tN);
    e_gemm_kernel<<<296, GTHREADS, SM_TOTAL>>>(ea, be, nE, tE);

    edge_kernel<<<4096, 256>>>(ei, pE, out, nE);

    int totalO = nN * DIM;
    normalize_kernel<<<(totalO + 255) / 256, 256>>>(out, totalO);
}